// round 9
// baseline (speedup 1.0000x reference)
#include <cuda_runtime.h>

#define KS 7
#define PAD 3
#define TILE_W 128
#define TILE_H 32
#define SW 136                     // staged row: gx in [bx-4, bx+132)
#define SH 38                      // 32 + 6 halo rows
#define ROW_CHUNKS 34              // 34 x 16B per row
#define TCHUNKS (SH * ROW_CHUNKS)  // 1292
#define NTILES 4096                // 8x * 32y * 16b
#define GRID_CTAS 608              // 4 per SM
#define CTA_THREADS 256
#define BUF_FLOATS (SH * SW)       // 5168
#define SMEM_BYTES (2 * BUF_FLOATS * 4 + 49 * 8)

typedef unsigned long long u64;

__device__ __forceinline__ u64 pk2(float lo, float hi) {
    u64 r; asm("mov.b64 %0, {%1,%2};" : "=l"(r) : "f"(lo), "f"(hi)); return r;
}
__device__ __forceinline__ void fma2(u64& d, u64 a, u64 b) {
    asm("fma.rn.f32x2 %0, %1, %2, %0;" : "+l"(d) : "l"(a), "l"(b));
}
__device__ __forceinline__ void unpk2(u64 v, float& lo, float& hi) {
    asm("mov.b64 {%0,%1}, %2;" : "=f"(lo), "=f"(hi) : "l"(v));
}
__device__ __forceinline__ void cpa16(unsigned dst, const float* src, unsigned nbytes) {
    asm volatile("cp.async.ca.shared.global [%0], [%1], 16, %2;"
                 :: "r"(dst), "l"(src), "r"(nbytes) : "memory");
}

extern __shared__ float smem[];

__device__ __forceinline__ void stage_tile(const float* __restrict__ img, int t,
                                           unsigned sbuf, int tid) {
    int b   = t >> 8;              // 256 tiles per image (8x * 32y)
    int rem = t & 255;
    int by  = (rem >> 3) * TILE_H;
    int bx  = (rem & 7) * TILE_W;
    const float* src = img + ((size_t)b * 3 + 2) * (size_t)(1024 * 1024); // last channel

    #pragma unroll
    for (int k = 0; k < 6; k++) {
        int i = tid + k * CTA_THREADS;
        if (i < TCHUNKS) {
            int r  = i / ROW_CHUNKS;
            int c  = i - r * ROW_CHUNKS;
            int gy = by + r - PAD;
            int gx = bx - 4 + c * 4;
            unsigned ok = ((unsigned)gy < 1024u && (unsigned)gx < 1024u) ? 16u : 0u;
            const float* p = src + (size_t)(gy & 1023) * 1024 + (gx & 1023);
            cpa16(sbuf + (unsigned)(r * SW + c * 4) * 4u, p, ok);
        }
    }
    asm volatile("cp.async.commit_group;" ::: "memory");
}

__global__ __launch_bounds__(CTA_THREADS, 4)
void Conv_8443905704574_kernel(const float* __restrict__ img,
                               const float* __restrict__ ker,
                               float* __restrict__ out) {
    const int tid = threadIdx.x;
    float* buf0 = smem;
    float* buf1 = smem + BUF_FLOATS;
    u64*   kw2  = (u64*)(smem + 2 * BUF_FLOATS);

    if (tid < 49) {
        float w = ker[tid];
        kw2[tid] = pk2(w, w);
    }

    unsigned sbase;
    asm("{ .reg .u64 t; cvta.to.shared.u64 t, %1; cvt.u32.u64 %0, t; }"
        : "=r"(sbase) : "l"(smem));
    const unsigned sb0 = sbase;
    const unsigned sb1 = sbase + BUF_FLOATS * 4;

    const int tx   = tid & 31;   // 4 contiguous x px, 16B/lane (conflict-free)
    const int ty   = tid >> 5;   // 0..7
    const int row0 = ty * 4;     // 4 output rows per thread

    int t = blockIdx.x;
    if (t < NTILES) stage_tile(img, t, sb0, tid);
    int cur = 0;

    while (t < NTILES) {
        int nxt = t + GRID_CTAS;
        if (nxt < NTILES) {
            stage_tile(img, nxt, cur ? sb0 : sb1, tid);
            asm volatile("cp.async.wait_group 1;" ::: "memory");
        } else {
            asm volatile("cp.async.wait_group 0;" ::: "memory");
        }
        __syncthreads();

        const float* B = cur ? buf1 : buf0;

        u64 acc01[4], acc23[4];
        #pragma unroll
        for (int o = 0; o < 4; o++) { acc01[o] = 0ull; acc23[o] = 0ull; }

        // sliding 10-row window; each input row loaded once, feeds up to 4 output rows
        #pragma unroll
        for (int r = 0; r < 10; r++) {
            const float* row = B + (row0 + r) * SW + tx * 4;
            float4 A0 = *(const float4*)(row);
            float4 A1 = *(const float4*)(row + 4);
            float4 A2 = *(const float4*)(row + 8);      // v[8..11]; v[11] unused
            float v[12] = {A0.x, A0.y, A0.z, A0.w, A1.x, A1.y, A1.z, A1.w,
                           A2.x, A2.y, A2.z, A2.w};
            u64 P[9];
            #pragma unroll
            for (int i = 0; i < 9; i++) P[i] = pk2(v[i + 1], v[i + 2]);

            #pragma unroll
            for (int o = 0; o < 4; o++) {
                const int ky = r - o;
                if (ky >= 0 && ky < KS) {
                    #pragma unroll
                    for (int kx = 0; kx < KS; kx++) {
                        u64 ww = kw2[ky * 7 + kx];   // LDS.64 broadcast, feeds 2 fma2
                        fma2(acc01[o], P[kx],     ww);
                        fma2(acc23[o], P[kx + 2], ww);
                    }
                }
            }
        }

        // Barrier BEFORE stores: smem reads done; store drain overlaps next staging.
        __syncthreads();

        int b   = t >> 8;
        int rem = t & 255;
        int by  = (rem >> 3) * TILE_H;
        int bx  = (rem & 7) * TILE_W;
        int ox  = bx + tx * 4;
        size_t obase = (size_t)b * 3 * 1024 * 1024;
        #pragma unroll
        for (int o = 0; o < 4; o++) {
            float4 r4;
            unpk2(acc01[o], r4.x, r4.y);
            unpk2(acc23[o], r4.z, r4.w);
            size_t off = obase + (size_t)(by + row0 + o) * 1024 + ox;
            #pragma unroll
            for (int c = 0; c < 3; c++)
                __stcs((float4*)(out + off + (size_t)c * 1024 * 1024), r4);
        }

        cur ^= 1;
        t = nxt;
    }
}

extern "C" void kernel_launch(void* const* d_in, const int* in_sizes, int n_in,
                              void* d_out, int out_size) {
    const float* img = (const float*)d_in[0];
    const float* ker = (const float*)d_in[1];
    float* out = (float*)d_out;

    cudaFuncSetAttribute(Conv_8443905704574_kernel,
                         cudaFuncAttributeMaxDynamicSharedMemorySize, SMEM_BYTES);
    Conv_8443905704574_kernel<<<GRID_CTAS, CTA_THREADS, SMEM_BYTES>>>(img, ker, out);
}

// round 10
// speedup vs baseline: 1.1590x; 1.1590x over previous
#include <cuda_runtime.h>

#define KS 7
#define TILE_W 128
#define TILE_H 64

typedef unsigned long long u64;

__device__ __forceinline__ u64 pk2(float lo, float hi) {
    u64 r; asm("mov.b64 %0, {%1,%2};" : "=l"(r) : "f"(lo), "f"(hi)); return r;
}
__device__ __forceinline__ void fma2(u64& d, u64 a, u64 b) {
    asm("fma.rn.f32x2 %0, %1, %2, %0;" : "+l"(d) : "l"(a), "l"(b));
}
__device__ __forceinline__ void unpk2(u64 v, float& lo, float& hi) {
    asm("mov.b64 {%0,%1}, %2;" : "=f"(lo), "=f"(hi) : "l"(v));
}

__global__ __launch_bounds__(512, 2)
void Conv_8443905704574_kernel(const float* __restrict__ img,
                               const float* __restrict__ ker,
                               float* __restrict__ out) {
    __shared__ u64 kw2[49];

    const int tid = threadIdx.x;
    if (tid < 49) {
        float w = ker[tid];
        kw2[tid] = pk2(w, w);
    }
    __syncthreads();             // only barrier in the kernel

    const int tx   = tid & 31;   // 4 contiguous output px per thread
    const int ty   = tid >> 5;   // 0..15
    const int bx   = blockIdx.x * TILE_W;
    const int by   = blockIdx.y * TILE_H;
    const int b    = blockIdx.z;
    const int row0 = by + ty * 4;           // first output row (global)
    const int col0 = bx + tx * 4 - 4;       // aligned read base (global), mult of 4

    // reference convolves only the LAST channel and broadcasts it
    const float* __restrict__ src = img + ((size_t)b * 3 + 2) * (size_t)(1024 * 1024);

    u64 acc01[4], acc23[4];
    #pragma unroll
    for (int o = 0; o < 4; o++) { acc01[o] = 0ull; acc23[o] = 0ull; }

    const bool xok0 = (unsigned)(col0)     < 1024u;  // only false at left image edge
    const bool xok2 = (unsigned)(col0 + 8) < 1024u;  // only false at right image edge
    // middle chunk col0+4 .. col0+7 is always in [0,1024): bx>=0 -> col0+4 >= 0; col0+7 <= 1023+... 
    // col0 max = 896+124-4 = 1016 -> col0+7 = 1023 ✓

    // sliding 10-row window; each input row read once, feeds up to 4 output rows
    #pragma unroll
    for (int r = 0; r < 10; r++) {
        const int gy = row0 + r - 3;
        const bool yok = (unsigned)gy < 1024u;
        const float* p = src + (size_t)(gy & 1023) * 1024 + col0;

        const float4 Z = make_float4(0.f, 0.f, 0.f, 0.f);
        float4 A0 = (yok && xok0) ? *(const float4*)(p)     : Z;
        float4 A1 =  yok          ? *(const float4*)(p + 4) : Z;
        float4 A2 = (yok && xok2) ? *(const float4*)(p + 8) : Z;

        float v[12] = {A0.x, A0.y, A0.z, A0.w, A1.x, A1.y, A1.z, A1.w,
                       A2.x, A2.y, A2.z, A2.w};
        u64 P[9];
        #pragma unroll
        for (int i = 0; i < 9; i++) P[i] = pk2(v[i + 1], v[i + 2]);

        #pragma unroll
        for (int o = 0; o < 4; o++) {
            const int ky = r - o;
            if (ky >= 0 && ky < KS) {
                #pragma unroll
                for (int kx = 0; kx < KS; kx++) {
                    u64 ww = kw2[ky * 7 + kx];   // LDS.64 broadcast, feeds 2 fma2
                    fma2(acc01[o], P[kx],     ww);
                    fma2(acc23[o], P[kx + 2], ww);
                }
            }
        }
    }

    const int ox = bx + tx * 4;
    size_t obase = (size_t)b * 3 * 1024 * 1024;
    #pragma unroll
    for (int o = 0; o < 4; o++) {
        float4 r4;
        unpk2(acc01[o], r4.x, r4.y);
        unpk2(acc23[o], r4.z, r4.w);
        size_t off = obase + (size_t)(row0 + o) * 1024 + ox;
        #pragma unroll
        for (int c = 0; c < 3; c++)
            __stcs((float4*)(out + off + (size_t)c * 1024 * 1024), r4);
    }
}

extern "C" void kernel_launch(void* const* d_in, const int* in_sizes, int n_in,
                              void* d_out, int out_size) {
    const float* img = (const float*)d_in[0];
    const float* ker = (const float*)d_in[1];
    float* out = (float*)d_out;

    dim3 grid(1024 / TILE_W, 1024 / TILE_H, 16);   // 8 x 16 x 16 = 2048 CTAs
    Conv_8443905704574_kernel<<<grid, 512>>>(img, ker, out);
}